// round 1
// baseline (speedup 1.0000x reference)
#include <cuda_runtime.h>
#include <math.h>

// Problem constants
#define NT 8192          // tokens = 4*2048
#define NH 1024          // hidden
#define NE 8             // experts
#define NI 4096          // intermediate
#define NPAIRS (2*NT)    // top-2 pairs

// ---------------- device scratch (static; no allocations allowed) ----------------
__device__ int   g_sel[NT*2];
__device__ float g_wt[NT*2];
__device__ int   g_counts[NE];
__device__ int   g_offsets[NE];
__device__ int   g_cursor[NE];
__device__ float g_probsum[NE];
__device__ float g_zsum;
__device__ int   g_pair_tok[NPAIRS];
__device__ float g_pair_w[NPAIRS];
__device__ float g_h[NPAIRS * NI];   // 16384 x 4096 fp32 = 256 MB intermediate

// ---------------- init: zero accumulators + output region ----------------
__global__ void k_init(float* __restrict__ out) {
    int idx = blockIdx.x * blockDim.x + threadIdx.x;
    if (idx < NE) { g_counts[idx] = 0; g_cursor[idx] = 0; g_probsum[idx] = 0.f; }
    if (idx == 0) g_zsum = 0.f;
    const int n = NT * NH;
    for (int i = idx; i < n; i += gridDim.x * blockDim.x) out[i] = 0.f;
}

// ---------------- router: one warp per token ----------------
__global__ void k_router(const float* __restrict__ x, const float* __restrict__ gw) {
    __shared__ float sgw[NE * NH];   // 32 KB
    __shared__ float sprob[NE];
    __shared__ float sz;
    int tid = threadIdx.x;
    for (int i = tid; i < NE * NH; i += 256) sgw[i] = gw[i];
    if (tid < NE) sprob[tid] = 0.f;
    if (tid == 0) sz = 0.f;
    __syncthreads();

    int warp = tid >> 5, lane = tid & 31;
    int t = blockIdx.x * 8 + warp;

    float acc[NE];
#pragma unroll
    for (int e = 0; e < NE; e++) acc[e] = 0.f;
    const float* xr = x + (size_t)t * NH;
    for (int j = lane; j < NH; j += 32) {
        float xv = xr[j];
#pragma unroll
        for (int e = 0; e < NE; e++) acc[e] += xv * sgw[e * NH + j];
    }
#pragma unroll
    for (int e = 0; e < NE; e++) {
#pragma unroll
        for (int off = 16; off > 0; off >>= 1)
            acc[e] += __shfl_xor_sync(0xffffffffu, acc[e], off);
    }

    if (lane == 0) {
        float m = acc[0];
#pragma unroll
        for (int e = 1; e < NE; e++) m = fmaxf(m, acc[e]);
        float p[NE]; float s = 0.f;
#pragma unroll
        for (int e = 0; e < NE; e++) { p[e] = expf(acc[e] - m); s += p[e]; }
        float inv = 1.f / s;
#pragma unroll
        for (int e = 0; e < NE; e++) p[e] *= inv;

        // top-2, stable (first occurrence wins on ties, matches lax.top_k)
        int i0 = 0; float m0 = p[0];
#pragma unroll
        for (int e = 1; e < NE; e++) if (p[e] > m0) { m0 = p[e]; i0 = e; }
        int i1 = -1; float m1 = -1.f;
#pragma unroll
        for (int e = 0; e < NE; e++) if (e != i0 && p[e] > m1) { m1 = p[e]; i1 = e; }

        float wsum = m0 + m1;
        g_sel[2*t]   = i0;  g_sel[2*t+1] = i1;
        g_wt [2*t]   = m0 / wsum;
        g_wt [2*t+1] = m1 / wsum;
        atomicAdd(&g_counts[i0], 1);
        atomicAdd(&g_counts[i1], 1);
#pragma unroll
        for (int e = 0; e < NE; e++) atomicAdd(&sprob[e], p[e]);
        float lse = m + logf(s);
        atomicAdd(&sz, lse * lse);
    }
    __syncthreads();
    if (tid < NE) atomicAdd(&g_probsum[tid], sprob[tid]);
    if (tid == 0) atomicAdd(&g_zsum, sz);
}

// ---------------- offsets (exclusive prefix over 8 experts) ----------------
__global__ void k_offsets() {
    if (threadIdx.x == 0 && blockIdx.x == 0) {
        int s = 0;
        for (int e = 0; e < NE; e++) { g_offsets[e] = s; s += g_counts[e]; }
    }
}

// ---------------- scatter tokens into per-expert compact lists ----------------
__global__ void k_scatter() {
    int t = blockIdx.x * blockDim.x + threadIdx.x;
    if (t >= NT) return;
#pragma unroll
    for (int k = 0; k < 2; k++) {
        int e = g_sel[2*t + k];
        int pos = atomicAdd(&g_cursor[e], 1);
        int p = g_offsets[e] + pos;
        g_pair_tok[p] = t;
        g_pair_w[p]   = g_wt[2*t + k];
    }
}

// ---------------- pass 1: h = silu(x Wg^T) * (x Wu^T), gathered rows ----------------
#define P1_BM 128
#define P1_BN 64
#define P1_BK 16
#define TILES_M (NT / P1_BM)   // 64 tile-rows per expert (worst case)

__global__ void __launch_bounds__(256, 2)
k_ffn1(const float* __restrict__ x,
       const float* __restrict__ wg,
       const float* __restrict__ wu) {
    int e   = blockIdx.y / TILES_M;
    int tr  = blockIdx.y % TILES_M;
    int cnt = g_counts[e];
    int row0 = tr * P1_BM;
    if (row0 >= cnt) return;
    int base = g_offsets[e];
    int n0 = blockIdx.x * P1_BN;

    __shared__ __align__(16) float As[P1_BK][P1_BM + 4];   // +4 pad: keeps 16B align, breaks conflicts
    __shared__ __align__(16) float Bg[P1_BK][P1_BN + 4];
    __shared__ __align__(16) float Bu[P1_BK][P1_BN + 4];
    __shared__ int s_tok[P1_BM];

    int tid = threadIdx.x;
    if (tid < P1_BM) {
        int r = row0 + tid;
        s_tok[tid] = (r < cnt) ? g_pair_tok[base + r] : 0;  // clamp invalid to token 0 (safe)
    }
    __syncthreads();

    int rA0 = tid >> 2;          // 0..63
    int rA1 = rA0 + 64;
    int kq  = tid & 3;           // float4 slot within the 16-wide k tile

    const float* pA0 = x  + (size_t)s_tok[rA0] * NH + kq * 4;
    const float* pA1 = x  + (size_t)s_tok[rA1] * NH + kq * 4;
    const float* pBg = wg + ((size_t)e * NI + n0 + rA0) * NH + kq * 4;
    const float* pBu = wu + ((size_t)e * NI + n0 + rA0) * NH + kq * 4;

    float4 ra0 = *(const float4*)pA0;
    float4 ra1 = *(const float4*)pA1;
    float4 rg  = *(const float4*)pBg;
    float4 ru  = *(const float4*)pBu;

    int tm = tid >> 4, tn = tid & 15;
    int m0 = tm * 8, nn = tn * 4;

    float accg[8][4], accu[8][4];
#pragma unroll
    for (int i = 0; i < 8; i++)
#pragma unroll
        for (int j = 0; j < 4; j++) { accg[i][j] = 0.f; accu[i][j] = 0.f; }

    const int KT = NH / P1_BK;   // 64
    for (int kt = 0; kt < KT; kt++) {
        int kb = kq * 4;
        As[kb+0][rA0] = ra0.x; As[kb+1][rA0] = ra0.y; As[kb+2][rA0] = ra0.z; As[kb+3][rA0] = ra0.w;
        As[kb+0][rA1] = ra1.x; As[kb+1][rA1] = ra1.y; As[kb+2][rA1] = ra1.z; As[kb+3][rA1] = ra1.w;
        Bg[kb+0][rA0] = rg.x;  Bg[kb+1][rA0] = rg.y;  Bg[kb+2][rA0] = rg.z;  Bg[kb+3][rA0] = rg.w;
        Bu[kb+0][rA0] = ru.x;  Bu[kb+1][rA0] = ru.y;  Bu[kb+2][rA0] = ru.z;  Bu[kb+3][rA0] = ru.w;
        __syncthreads();

        if (kt + 1 < KT) {
            int off = (kt + 1) * P1_BK;
            ra0 = *(const float4*)(pA0 + off);
            ra1 = *(const float4*)(pA1 + off);
            rg  = *(const float4*)(pBg + off);
            ru  = *(const float4*)(pBu + off);
        }

#pragma unroll
        for (int k = 0; k < P1_BK; k++) {
            float a[8];
            *(float4*)&a[0] = *(const float4*)&As[k][m0];
            *(float4*)&a[4] = *(const float4*)&As[k][m0 + 4];
            float4 bg4 = *(const float4*)&Bg[k][nn];
            float4 bu4 = *(const float4*)&Bu[k][nn];
            float bg[4] = {bg4.x, bg4.y, bg4.z, bg4.w};
            float bu[4] = {bu4.x, bu4.y, bu4.z, bu4.w};
#pragma unroll
            for (int i = 0; i < 8; i++)
#pragma unroll
                for (int j = 0; j < 4; j++) {
                    accg[i][j] += a[i] * bg[j];
                    accu[i][j] += a[i] * bu[j];
                }
        }
        __syncthreads();
    }

    // epilogue: h = silu(g) * u  (silu(g) = g * sigmoid(g))
#pragma unroll
    for (int i = 0; i < 8; i++) {
        int r = row0 + m0 + i;
        if (r < cnt) {
            float4 hv;
            float g0 = accg[i][0], g1 = accg[i][1], g2 = accg[i][2], g3 = accg[i][3];
            hv.x = g0 / (1.f + expf(-g0)) * accu[i][0];
            hv.y = g1 / (1.f + expf(-g1)) * accu[i][1];
            hv.z = g2 / (1.f + expf(-g2)) * accu[i][2];
            hv.w = g3 / (1.f + expf(-g3)) * accu[i][3];
            *(float4*)&g_h[(size_t)(base + r) * NI + n0 + nn] = hv;
        }
    }
}

// ---------------- pass 2: out[t] += w * (h @ Wd^T) ----------------
#define P2_BM 128
#define P2_BN 128
#define P2_BK 16

__global__ void __launch_bounds__(256, 2)
k_ffn2(const float* __restrict__ wd, float* __restrict__ out) {
    int e   = blockIdx.y / TILES_M;
    int tr  = blockIdx.y % TILES_M;
    int cnt = g_counts[e];
    int row0 = tr * P2_BM;
    if (row0 >= cnt) return;
    int base = g_offsets[e];
    int n0 = blockIdx.x * P2_BN;

    __shared__ __align__(16) float As[P2_BK][P2_BM + 4];
    __shared__ __align__(16) float Bs[P2_BK][P2_BN + 4];
    __shared__ int   s_tok[P2_BM];
    __shared__ float s_w[P2_BM];

    int tid = threadIdx.x;
    if (tid < P2_BM) {
        int r = row0 + tid;
        s_tok[tid] = (r < cnt) ? g_pair_tok[base + r] : 0;
        s_w[tid]   = (r < cnt) ? g_pair_w[base + r] : 0.f;
    }
    __syncthreads();

    int rA0 = tid >> 2;       // 0..63
    int rA1 = rA0 + 64;
    int kq  = tid & 3;

    int rr0 = row0 + rA0; if (rr0 >= cnt) rr0 = cnt - 1;   // clamp reads into valid scratch
    int rr1 = row0 + rA1; if (rr1 >= cnt) rr1 = cnt - 1;

    const float* pA0 = g_h + (size_t)(base + rr0) * NI + kq * 4;
    const float* pA1 = g_h + (size_t)(base + rr1) * NI + kq * 4;
    const float* pB0 = wd + ((size_t)e * NH + n0 + rA0) * NI + kq * 4;
    const float* pB1 = wd + ((size_t)e * NH + n0 + rA1) * NI + kq * 4;

    float4 ra0 = *(const float4*)pA0;
    float4 ra1 = *(const float4*)pA1;
    float4 rb0 = *(const float4*)pB0;
    float4 rb1 = *(const float4*)pB1;

    int tm = tid >> 4, tn = tid & 15;
    int m0 = tm * 8, nn = tn * 8;

    float acc[8][8];
#pragma unroll
    for (int i = 0; i < 8; i++)
#pragma unroll
        for (int j = 0; j < 8; j++) acc[i][j] = 0.f;

    const int KT = NI / P2_BK;   // 256
    for (int kt = 0; kt < KT; kt++) {
        int kb = kq * 4;
        As[kb+0][rA0] = ra0.x; As[kb+1][rA0] = ra0.y; As[kb+2][rA0] = ra0.z; As[kb+3][rA0] = ra0.w;
        As[kb+0][rA1] = ra1.x; As[kb+1][rA1] = ra1.y; As[kb+2][rA1] = ra1.z; As[kb+3][rA1] = ra1.w;
        Bs[kb+0][rA0] = rb0.x; Bs[kb+1][rA0] = rb0.y; Bs[kb+2][rA0] = rb0.z; Bs[kb+3][rA0] = rb0.w;
        Bs[kb+0][rA1] = rb1.x; Bs[kb+1][rA1] = rb1.y; Bs[kb+2][rA1] = rb1.z; Bs[kb+3][rA1] = rb1.w;
        __syncthreads();

        if (kt + 1 < KT) {
            int off = (kt + 1) * P2_BK;
            ra0 = *(const float4*)(pA0 + off);
            ra1 = *(const float4*)(pA1 + off);
            rb0 = *(const float4*)(pB0 + off);
            rb1 = *(const float4*)(pB1 + off);
        }

#pragma unroll
        for (int k = 0; k < P2_BK; k++) {
            float a[8], b[8];
            *(float4*)&a[0] = *(const float4*)&As[k][m0];
            *(float4*)&a[4] = *(const float4*)&As[k][m0 + 4];
            *(float4*)&b[0] = *(const float4*)&Bs[k][nn];
            *(float4*)&b[4] = *(const float4*)&Bs[k][nn + 4];
#pragma unroll
            for (int i = 0; i < 8; i++)
#pragma unroll
                for (int j = 0; j < 8; j++) acc[i][j] += a[i] * b[j];
        }
        __syncthreads();
    }

    // epilogue: weighted accumulate (each token appears in exactly 2 expert lists)
#pragma unroll
    for (int i = 0; i < 8; i++) {
        int r = row0 + m0 + i;
        if (r < cnt) {
            int   t = s_tok[m0 + i];
            float w = s_w[m0 + i];
            float* orow = out + (size_t)t * NH + n0 + nn;
#pragma unroll
            for (int j = 0; j < 8; j++) atomicAdd(&orow[j], w * acc[i][j]);
        }
    }
}

// ---------------- losses ----------------
__global__ void k_losses(float* __restrict__ out, int out_size) {
    if (threadIdx.x == 0 && blockIdx.x == 0) {
        float lb = 0.f;
        for (int e = 0; e < NE; e++)
            lb += ((float)g_counts[e] / (float)NT) * (g_probsum[e] / (float)NT);
        lb *= (float)NE * 0.01f;
        float z = g_zsum / (float)NT * 0.001f;
        if (out_size > NT * NH)     out[NT * NH]     = lb;
        if (out_size > NT * NH + 1) out[NT * NH + 1] = z;
    }
}

// ---------------- launch ----------------
extern "C" void kernel_launch(void* const* d_in, const int* in_sizes, int n_in,
                              void* d_out, int out_size) {
    const float* x  = (const float*)d_in[0];   // [4,2048,1024]
    const float* gw = (const float*)d_in[1];   // [8,1024]
    const float* wg = (const float*)d_in[2];   // [8,4096,1024]
    const float* wu = (const float*)d_in[3];   // [8,4096,1024]
    const float* wd = (const float*)d_in[4];   // [8,1024,4096]
    float* out = (float*)d_out;

    k_init<<<2048, 256>>>(out);
    k_router<<<NT / 8, 256>>>(x, gw);
    k_offsets<<<1, 32>>>();
    k_scatter<<<(NT + 255) / 256, 256>>>();

    dim3 g1(NI / P1_BN, NE * TILES_M);   // (64, 512)
    k_ffn1<<<g1, 256>>>(x, wg, wu);

    dim3 g2(NH / P2_BN, NE * TILES_M);   // (8, 512)
    k_ffn2<<<g2, 256>>>(wd, out);

    k_losses<<<1, 32>>>(out, out_size);
}

// round 5
// speedup vs baseline: 4.5460x; 4.5460x over previous
#include <cuda_runtime.h>
#include <cuda_fp16.h>
#include <cstdint>
#include <math.h>

// Problem constants
#define NT 8192          // tokens = 4*2048
#define NH 1024          // hidden
#define NE 8             // experts
#define NI 4096          // intermediate
#define NPAIRS (2*NT)    // top-2 pairs

// mma.sync m16n8k16 row.col f32.f16.f16.f32
__device__ __forceinline__ void mma16816(float* d, const uint32_t* a, const uint32_t* b) {
    asm volatile("mma.sync.aligned.m16n8k16.row.col.f32.f16.f16.f32 "
        "{%0,%1,%2,%3}, {%4,%5,%6,%7}, {%8,%9}, {%0,%1,%2,%3};"
        : "+f"(d[0]), "+f"(d[1]), "+f"(d[2]), "+f"(d[3])
        : "r"(a[0]), "r"(a[1]), "r"(a[2]), "r"(a[3]), "r"(b[0]), "r"(b[1]));
}

// ==================== device scratch (all 16B-aligned) ====================
__device__ __align__(16) int   g_sel[NT * 2];
__device__ __align__(16) float g_wt[NT * 2];
__device__ __align__(16) int   g_counts[NE];
__device__ __align__(16) int   g_offsets[NE];
__device__ __align__(16) int   g_cursor[NE];
__device__ __align__(16) float g_probsum[NE];
__device__ float g_zsum;
__device__ __align__(16) int   g_pair_tok[NPAIRS];
__device__ __align__(16) float g_pair_w[NPAIRS];

__device__ __align__(16) __half g_x_h[NT * NH];
__device__ __align__(16) __half g_wg_h[NE * NI * NH];
__device__ __align__(16) __half g_wu_h[NE * NI * NH];
__device__ __align__(16) __half g_wd_h[NE * NH * NI];
__device__ __align__(16) __half g_h[(size_t)NPAIRS * NI];

// ==================== init ====================
__global__ void k_init(float* __restrict__ out) {
    int idx = blockIdx.x * blockDim.x + threadIdx.x;
    if (idx < NE) { g_counts[idx] = 0; g_cursor[idx] = 0; g_probsum[idx] = 0.f; }
    if (idx == 0) g_zsum = 0.f;
    const int n = NT * NH;
    for (int i = idx; i < n; i += gridDim.x * blockDim.x) out[i] = 0.f;
}

// ==================== fp32 -> fp16 ====================
// CRITICAL: destination resolved IN DEVICE CODE. Passing a __device__ array
// as a host-side kernel argument passes the host shadow address; on GB300
// (ATS-coherent) the writes silently land in host memory and the device
// arrays stay zero. That was the R3/R4 failure.
__global__ void k_half(const float* __restrict__ src, int which, int n4) {
    __half* dst;
    switch (which) {
        case 0:  dst = g_wg_h; break;
        case 1:  dst = g_wu_h; break;
        case 2:  dst = g_wd_h; break;
        default: dst = g_x_h;  break;
    }
    int i = blockIdx.x * blockDim.x + threadIdx.x;
    if (i >= n4) return;
    float4 v = ((const float4*)src)[i];
    union { __half h[4]; uint2 u; } r;
    r.h[0] = __float2half_rn(v.x);
    r.h[1] = __float2half_rn(v.y);
    r.h[2] = __float2half_rn(v.z);
    r.h[3] = __float2half_rn(v.w);
    ((uint2*)dst)[i] = r.u;
}

// ==================== router (one warp per token) ====================
__global__ void k_router(const float* __restrict__ x, const float* __restrict__ gw) {
    __shared__ float sgw[NE * NH];
    __shared__ float sprob[NE];
    __shared__ float sz;
    int tid = threadIdx.x;
    for (int i = tid; i < NE * NH; i += 256) sgw[i] = gw[i];
    if (tid < NE) sprob[tid] = 0.f;
    if (tid == 0) sz = 0.f;
    __syncthreads();

    int warp = tid >> 5, lane = tid & 31;
    int t = blockIdx.x * 8 + warp;

    float acc[NE];
#pragma unroll
    for (int e = 0; e < NE; e++) acc[e] = 0.f;
    const float* xr = x + (size_t)t * NH;
    for (int j = lane; j < NH; j += 32) {
        float xv = xr[j];
#pragma unroll
        for (int e = 0; e < NE; e++) acc[e] += xv * sgw[e * NH + j];
    }
#pragma unroll
    for (int e = 0; e < NE; e++)
#pragma unroll
        for (int off = 16; off > 0; off >>= 1)
            acc[e] += __shfl_xor_sync(0xffffffffu, acc[e], off);

    if (lane == 0) {
        float m = acc[0];
#pragma unroll
        for (int e = 1; e < NE; e++) m = fmaxf(m, acc[e]);
        float p[NE]; float s = 0.f;
#pragma unroll
        for (int e = 0; e < NE; e++) { p[e] = expf(acc[e] - m); s += p[e]; }
        float inv = 1.f / s;
#pragma unroll
        for (int e = 0; e < NE; e++) p[e] *= inv;

        int i0 = 0; float m0 = p[0];
#pragma unroll
        for (int e = 1; e < NE; e++) if (p[e] > m0) { m0 = p[e]; i0 = e; }
        int i1 = -1; float m1 = -1.f;
#pragma unroll
        for (int e = 0; e < NE; e++) if (e != i0 && p[e] > m1) { m1 = p[e]; i1 = e; }

        float wsum = m0 + m1;
        g_sel[2*t] = i0; g_sel[2*t+1] = i1;
        g_wt[2*t] = m0 / wsum; g_wt[2*t+1] = m1 / wsum;
        atomicAdd(&g_counts[i0], 1);
        atomicAdd(&g_counts[i1], 1);
#pragma unroll
        for (int e = 0; e < NE; e++) atomicAdd(&sprob[e], p[e]);
        float lse = m + logf(s);
        atomicAdd(&sz, lse * lse);
    }
    __syncthreads();
    if (tid < NE) atomicAdd(&g_probsum[tid], sprob[tid]);
    if (tid == 0) atomicAdd(&g_zsum, sz);
}

__global__ void k_offsets() {
    if (threadIdx.x == 0 && blockIdx.x == 0) {
        int s = 0;
        for (int e = 0; e < NE; e++) { g_offsets[e] = s; s += g_counts[e]; }
    }
}

__global__ void k_scatter() {
    int t = blockIdx.x * blockDim.x + threadIdx.x;
    if (t >= NT) return;
#pragma unroll
    for (int k = 0; k < 2; k++) {
        int e = g_sel[2*t + k];
        int pos = atomicAdd(&g_cursor[e], 1);
        int p = g_offsets[e] + pos;
        g_pair_tok[p] = t;
        g_pair_w[p]   = g_wt[2*t + k];
    }
}

// ==================== HMMA GEMM kernels (static smem, reg double-buffer) ====
#define KB 32                 // K elements per stage
#define PITCH 80              // bytes per row: 64 data + 16 pad (conflict-free frags)
#define TILES_M 64

// ---- pass 1: gate/up GEMM + SwiGLU -> g_h (fp16) ----
// CTA tile M=128 x N=64 (two outputs); 256 threads; grid (TILES_M, NE*64)
__global__ void __launch_bounds__(256) k_ffn1() {
    // stage: A 128*80=10240, Bg 64*80=5120, Bu 5120 => 20480; x2 stages
    __shared__ __align__(16) char smc[2 * 20480];
    __shared__ int s_tok[128];

    int e  = blockIdx.y >> 6;
    int n0 = (blockIdx.y & 63) * 64;
    int row0 = blockIdx.x * 128;
    int cnt = g_counts[e];
    if (row0 >= cnt) return;
    int base = g_offsets[e];
    int tid = threadIdx.x;

    if (tid < 128) {
        int r = row0 + tid;
        s_tok[tid] = g_pair_tok[base + (r < cnt ? r : cnt - 1)];
    }
    __syncthreads();

    // loaders: A: 512 chunks (2/thread); Bg,Bu: 256 chunks (1/thread)
    int a_r0 = tid >> 2;            // row 0..63
    int a_r1 = (tid + 256) >> 2;    // row 64..127
    int a_c  = tid & 3;
    int b_r  = tid >> 2;            // 0..63
    const __half* pA0 = g_x_h + (size_t)s_tok[a_r0] * NH + a_c * 8;
    const __half* pA1 = g_x_h + (size_t)s_tok[a_r1] * NH + a_c * 8;
    const __half* pBg = g_wg_h + ((size_t)e * NI + n0 + b_r) * NH + a_c * 8;
    const __half* pBu = g_wu_h + ((size_t)e * NI + n0 + b_r) * NH + a_c * 8;
    uint32_t sA0 = a_r0 * PITCH + a_c * 16;
    uint32_t sA1 = a_r1 * PITCH + a_c * 16;
    uint32_t sBg = 10240 + b_r * PITCH + a_c * 16;
    uint32_t sBu = 15360 + b_r * PITCH + a_c * 16;

    int lane = tid & 31, w = tid >> 5;
    int wm = w >> 1, wn = w & 1;
    int r4 = lane >> 2, c2 = lane & 3;

    float ag[2][4][4], au[2][4][4];
#pragma unroll
    for (int i = 0; i < 2; i++)
#pragma unroll
        for (int j = 0; j < 4; j++)
#pragma unroll
            for (int q = 0; q < 4; q++) { ag[i][j][q] = 0.f; au[i][j][q] = 0.f; }

    uint4 vA0 = *(const uint4*)pA0;
    uint4 vA1 = *(const uint4*)pA1;
    uint4 vBg = *(const uint4*)pBg;
    uint4 vBu = *(const uint4*)pBu;

    const int KT = NH / KB;   // 32
    for (int kt = 0; kt < KT; kt++) {
        char* stg = smc + (kt & 1) * 20480;
        *(uint4*)(stg + sA0) = vA0;
        *(uint4*)(stg + sA1) = vA1;
        *(uint4*)(stg + sBg) = vBg;
        *(uint4*)(stg + sBu) = vBu;
        __syncthreads();

        if (kt + 1 < KT) {
            int ko = (kt + 1) * KB;
            vA0 = *(const uint4*)(pA0 + ko);
            vA1 = *(const uint4*)(pA1 + ko);
            vBg = *(const uint4*)(pBg + ko);
            vBu = *(const uint4*)(pBu + ko);
        }

        const char* A_s  = stg;
        const char* Bg_s = stg + 10240;
        const char* Bu_s = stg + 15360;
#pragma unroll
        for (int kk = 0; kk < 2; kk++) {
            uint32_t af[2][4];
#pragma unroll
            for (int i = 0; i < 2; i++) {
                const char* ab = A_s + (wm * 32 + i * 16 + r4) * PITCH + kk * 32 + c2 * 4;
                af[i][0] = *(const uint32_t*)(ab);
                af[i][1] = *(const uint32_t*)(ab + 8 * PITCH);
                af[i][2] = *(const uint32_t*)(ab + 16);
                af[i][3] = *(const uint32_t*)(ab + 8 * PITCH + 16);
            }
#pragma unroll
            for (int j = 0; j < 4; j++) {
                int n = wn * 32 + j * 8 + r4;
                const char* bb = Bg_s + n * PITCH + kk * 32 + c2 * 4;
                uint32_t bg[2], bu[2];
                bg[0] = *(const uint32_t*)(bb);
                bg[1] = *(const uint32_t*)(bb + 16);
                const char* ub = Bu_s + n * PITCH + kk * 32 + c2 * 4;
                bu[0] = *(const uint32_t*)(ub);
                bu[1] = *(const uint32_t*)(ub + 16);
#pragma unroll
                for (int i = 0; i < 2; i++) {
                    mma16816(ag[i][j], af[i], bg);
                    mma16816(au[i][j], af[i], bu);
                }
            }
        }
        __syncthreads();
    }

    // epilogue: h = silu(g)*u -> fp16
#pragma unroll
    for (int i = 0; i < 2; i++)
#pragma unroll
        for (int rr = 0; rr < 2; rr++) {
            int rl = wm * 32 + i * 16 + r4 + rr * 8;
            int r = row0 + rl;
            if (r < cnt) {
                __half* hrow = g_h + (size_t)(base + r) * NI;
#pragma unroll
                for (int j = 0; j < 4; j++) {
                    int col = n0 + wn * 32 + j * 8 + c2 * 2;
                    float g0 = ag[i][j][rr * 2], g1 = ag[i][j][rr * 2 + 1];
                    float u0 = au[i][j][rr * 2], u1 = au[i][j][rr * 2 + 1];
                    float h0 = g0 / (1.f + expf(-g0)) * u0;
                    float h1 = g1 / (1.f + expf(-g1)) * u1;
                    *(__half2*)(hrow + col) = __floats2half2_rn(h0, h1);
                }
            }
        }
}

// ---- pass 2: out[tok] += w * (h @ Wd^T) ----
// CTA tile M=128 x N=128; 256 threads; grid (TILES_M, NE*8)
__global__ void __launch_bounds__(256) k_ffn2(float* __restrict__ out) {
    __shared__ __align__(16) char smc[2 * 20480];
    __shared__ int   s_tok[128];
    __shared__ float s_w[128];

    int e  = blockIdx.y >> 3;
    int n0 = (blockIdx.y & 7) * 128;
    int row0 = blockIdx.x * 128;
    int cnt = g_counts[e];
    if (row0 >= cnt) return;
    int base = g_offsets[e];
    int tid = threadIdx.x;

    if (tid < 128) {
        int r = row0 + tid;
        s_tok[tid] = (r < cnt) ? g_pair_tok[base + r] : 0;
        s_w[tid]   = (r < cnt) ? g_pair_w[base + r] : 0.f;
    }
    __syncthreads();

    int a_r0 = tid >> 2;
    int a_r1 = (tid + 256) >> 2;
    int a_c  = tid & 3;
    int rc0 = row0 + a_r0; if (rc0 >= cnt) rc0 = cnt - 1;
    int rc1 = row0 + a_r1; if (rc1 >= cnt) rc1 = cnt - 1;
    const __half* pA0 = g_h + (size_t)(base + rc0) * NI + a_c * 8;
    const __half* pA1 = g_h + (size_t)(base + rc1) * NI + a_c * 8;
    const __half* pB0 = g_wd_h + ((size_t)e * NH + n0 + a_r0) * NI + a_c * 8;
    const __half* pB1 = g_wd_h + ((size_t)e * NH + n0 + a_r1) * NI + a_c * 8;
    uint32_t sA0 = a_r0 * PITCH + a_c * 16;
    uint32_t sA1 = a_r1 * PITCH + a_c * 16;
    uint32_t sB0 = 10240 + sA0;
    uint32_t sB1 = 10240 + sA1;

    int lane = tid & 31, w = tid >> 5;
    int wm = w >> 1, wn = w & 1;
    int r4 = lane >> 2, c2 = lane & 3;

    float acc[2][8][4];
#pragma unroll
    for (int i = 0; i < 2; i++)
#pragma unroll
        for (int j = 0; j < 8; j++)
#pragma unroll
            for (int q = 0; q < 4; q++) acc[i][j][q] = 0.f;

    uint4 vA0 = *(const uint4*)pA0;
    uint4 vA1 = *(const uint4*)pA1;
    uint4 vB0 = *(const uint4*)pB0;
    uint4 vB1 = *(const uint4*)pB1;

    const int KT = NI / KB;   // 128
    for (int kt = 0; kt < KT; kt++) {
        char* stg = smc + (kt & 1) * 20480;
        *(uint4*)(stg + sA0) = vA0;
        *(uint4*)(stg + sA1) = vA1;
        *(uint4*)(stg + sB0) = vB0;
        *(uint4*)(stg + sB1) = vB1;
        __syncthreads();

        if (kt + 1 < KT) {
            int ko = (kt + 1) * KB;
            vA0 = *(const uint4*)(pA0 + ko);
            vA1 = *(const uint4*)(pA1 + ko);
            vB0 = *(const uint4*)(pB0 + ko);
            vB1 = *(const uint4*)(pB1 + ko);
        }

        const char* A_s = stg;
        const char* B_s = stg + 10240;
#pragma unroll
        for (int kk = 0; kk < 2; kk++) {
            uint32_t af[2][4];
#pragma unroll
            for (int i = 0; i < 2; i++) {
                const char* ab = A_s + (wm * 32 + i * 16 + r4) * PITCH + kk * 32 + c2 * 4;
                af[i][0] = *(const uint32_t*)(ab);
                af[i][1] = *(const uint32_t*)(ab + 8 * PITCH);
                af[i][2] = *(const uint32_t*)(ab + 16);
                af[i][3] = *(const uint32_t*)(ab + 8 * PITCH + 16);
            }
#pragma unroll
            for (int j = 0; j < 8; j++) {
                int n = wn * 64 + j * 8 + r4;
                const char* bb = B_s + n * PITCH + kk * 32 + c2 * 4;
                uint32_t b[2];
                b[0] = *(const uint32_t*)(bb);
                b[1] = *(const uint32_t*)(bb + 16);
#pragma unroll
                for (int i = 0; i < 2; i++) mma16816(acc[i][j], af[i], b);
            }
        }
        __syncthreads();
    }

    // epilogue: weighted atomic accumulate into out
#pragma unroll
    for (int i = 0; i < 2; i++)
#pragma unroll
        for (int rr = 0; rr < 2; rr++) {
            int rl = wm * 32 + i * 16 + r4 + rr * 8;
            if (row0 + rl < cnt) {
                int tok = s_tok[rl];
                float wt = s_w[rl];
                float* orow = out + (size_t)tok * NH + n0;
#pragma unroll
                for (int j = 0; j < 8; j++) {
                    int col = wn * 64 + j * 8 + c2 * 2;
                    atomicAdd(&orow[col],     wt * acc[i][j][rr * 2]);
                    atomicAdd(&orow[col + 1], wt * acc[i][j][rr * 2 + 1]);
                }
            }
        }
}

// ==================== losses ====================
__global__ void k_losses(float* __restrict__ out, int out_size) {
    if (threadIdx.x == 0 && blockIdx.x == 0) {
        float lb = 0.f;
        for (int e = 0; e < NE; e++)
            lb += ((float)g_counts[e] / (float)NT) * (g_probsum[e] / (float)NT);
        lb *= (float)NE * 0.01f;
        float z = g_zsum / (float)NT * 0.001f;
        if (out_size > NT * NH)     out[NT * NH]     = lb;
        if (out_size > NT * NH + 1) out[NT * NH + 1] = z;
    }
}

// ==================== launch ====================
extern "C" void kernel_launch(void* const* d_in, const int* in_sizes, int n_in,
                              void* d_out, int out_size) {
    const float* x  = (const float*)d_in[0];
    const float* gw = (const float*)d_in[1];
    const float* wg = (const float*)d_in[2];
    const float* wu = (const float*)d_in[3];
    const float* wd = (const float*)d_in[4];
    float* out = (float*)d_out;

    k_init<<<2048, 256>>>(out);

    const int WN4 = NE * NI * NH / 4;
    k_half<<<(WN4 + 255) / 256, 256>>>(wg, 0, WN4);
    k_half<<<(WN4 + 255) / 256, 256>>>(wu, 1, WN4);
    k_half<<<(WN4 + 255) / 256, 256>>>(wd, 2, WN4);
    const int XN4 = NT * NH / 4;
    k_half<<<(XN4 + 255) / 256, 256>>>(x, 3, XN4);

    k_router<<<NT / 8, 256>>>(x, gw);
    k_offsets<<<1, 32>>>();
    k_scatter<<<(NT + 255) / 256, 256>>>();

    dim3 g1(TILES_M, NE * 64);
    k_ffn1<<<g1, 256>>>();

    dim3 g2(TILES_M, NE * 8);
    k_ffn2<<<g2, 256>>>(out);

    k_losses<<<1, 32>>>(out, out_size);
}